// round 7
// baseline (speedup 1.0000x reference)
#include <cuda_runtime.h>
#include <cuda_fp16.h>
#include <cstdint>

#define Nn 8
#define Cc 128
#define Ll 1024
#define Kk 100
#define EPSf 1e-8f

// Normalized fp16 rows, [N, L, C] (256B per row).
__device__ __half g_zh[Nn * Ll * Cc];
__device__ __half g_ch[Nn * Ll * Cc];
// Full Gram matrices, fp32: [N, L, L] = 32MB.
__device__ float g_mat[(size_t)Nn * Ll * Ll];

// Fused: transpose + norm + normalize + fp16 convert, one pass over the input.
__global__ void __launch_bounds__(256) prep_k(const float* __restrict__ zsrc,
                                              const float* __restrict__ csrc) {
    __shared__ float tile[32][129];
    __shared__ float sp[8][32];
    __shared__ float srn[32];

    int zz = blockIdx.y;
    bool is_c = zz >= Nn;
    int n = is_c ? zz - Nn : zz;
    int ld      = is_c ? (Ll + 1) : Ll;
    int col_off = is_c ? 1 : 0;
    int t0 = blockIdx.x * 32;
    const float* s = (is_c ? csrc : zsrc) + (size_t)n * Cc * ld + col_off + t0;
    __half* d = (is_c ? g_ch : g_zh) + ((size_t)n * Ll + t0) * Cc;

    int tid = threadIdx.x;
    int tx  = tid & 31;
    int ty  = tid >> 5;

#pragma unroll
    for (int i = 0; i < 16; i++) {
        int ch = i * 8 + ty;
        tile[tx][ch] = s[(size_t)ch * ld + tx];
    }
    __syncthreads();

    float acc = 0.f;
#pragma unroll
    for (int i = 0; i < 16; i++) {
        float v = tile[tx][ty * 16 + i];
        acc += v * v;
    }
    sp[ty][tx] = acc;
    __syncthreads();
    if (tid < 32) {
        float sum = 0.f;
#pragma unroll
        for (int y = 0; y < 8; y++) sum += sp[y][tid];
        srn[tid] = 1.0f / fmaxf(sqrtf(sum), EPSf);
    }
    __syncthreads();

#pragma unroll
    for (int i = 0; i < 2; i++) {
        int linear = tid + i * 256;
        int t = linear >> 4;
        int k = linear & 15;
        float rn = srn[t];
        __half2 h[4];
#pragma unroll
        for (int q = 0; q < 4; q++) {
            float a = tile[t][k * 8 + 2 * q]     * rn;
            float b = tile[t][k * 8 + 2 * q + 1] * rn;
            h[q] = __floats2half2_rn(a, b);
        }
        ((uint4*)(d + (size_t)t * Cc))[k] = *(const uint4*)h;
    }
}

// GEMM: M_n = Chat_n (A, [L x 128]) @ Zhat_n^T (B rows, [L x 128]).
// CTA tile 64x64, 4 warps, each warp 32x32 (2 m-tiles x 4 n-tiles of m16n8k16).
// Whole K=128 staged in smem once; 8 k-steps.
#define LDH 136   // padded halves per smem row (272B, 16B-aligned, conflict-free)
__global__ void __launch_bounds__(128) gemm_k() {
    __shared__ __half As[64 * LDH];
    __shared__ __half Bs[64 * LDH];

    int n  = blockIdx.z;
    int i0 = blockIdx.y * 64;
    int j0 = blockIdx.x * 64;
    int tid  = threadIdx.x;
    int warp = tid >> 5;
    int lane = tid & 31;
    int wi = (warp >> 1) * 32;   // warp row offset in tile
    int wj = (warp & 1) * 32;    // warp col offset in tile

    // Stage A and B tiles (64 rows x 128 halves = 16KB each), uint4 loads.
    const uint4* Ag = (const uint4*)(g_ch + ((size_t)n * Ll + i0) * Cc);
    const uint4* Bg = (const uint4*)(g_zh + ((size_t)n * Ll + j0) * Cc);
    uint4* Asu = (uint4*)As;
    uint4* Bsu = (uint4*)Bs;
#pragma unroll
    for (int w = 0; w < 8; w++) {
        int linear = w * 128 + tid;       // 0..1023
        int r = linear >> 4;              // row 0..63
        int c = linear & 15;              // uint4 0..15
        Asu[r * (LDH / 8) + c] = Ag[r * 16 + c];
        Bsu[r * (LDH / 8) + c] = Bg[r * 16 + c];
    }
    __syncthreads();

    float d[2][4][4];
#pragma unroll
    for (int mt = 0; mt < 2; mt++)
#pragma unroll
        for (int nt = 0; nt < 4; nt++)
#pragma unroll
            for (int q = 0; q < 4; q++) d[mt][nt][q] = 0.f;

    // ldmatrix base addresses (lane-dependent).
    // A: addr = &As[wi + mt*16 + (lane&15)][k0 + (lane>>4)*8]
    // B: addr = &Bs[wj + nt*8  + (lane&7) ][k0 + ((lane>>3)&1)*8]
    uint32_t as_base = (uint32_t)__cvta_generic_to_shared(As);
    uint32_t bs_base = (uint32_t)__cvta_generic_to_shared(Bs);
    uint32_t a_lane_off = (uint32_t)((wi + (lane & 15)) * LDH + (lane >> 4) * 8) * 2;
    uint32_t b_lane_off = (uint32_t)((wj + (lane & 7)) * LDH + ((lane >> 3) & 1) * 8) * 2;

#pragma unroll
    for (int ks = 0; ks < 8; ks++) {
        uint32_t k0b = ks * 16 * 2;   // k offset in bytes

        uint32_t a[2][4];
#pragma unroll
        for (int mt = 0; mt < 2; mt++) {
            uint32_t addr = as_base + a_lane_off + (uint32_t)(mt * 16 * LDH) * 2 + k0b;
            asm volatile("ldmatrix.sync.aligned.m8n8.x4.shared.b16 {%0,%1,%2,%3}, [%4];"
                         : "=r"(a[mt][0]), "=r"(a[mt][1]), "=r"(a[mt][2]), "=r"(a[mt][3])
                         : "r"(addr));
        }
        uint32_t b[4][2];
#pragma unroll
        for (int nt = 0; nt < 4; nt++) {
            uint32_t addr = bs_base + b_lane_off + (uint32_t)(nt * 8 * LDH) * 2 + k0b;
            asm volatile("ldmatrix.sync.aligned.m8n8.x2.shared.b16 {%0,%1}, [%2];"
                         : "=r"(b[nt][0]), "=r"(b[nt][1])
                         : "r"(addr));
        }
#pragma unroll
        for (int mt = 0; mt < 2; mt++)
#pragma unroll
            for (int nt = 0; nt < 4; nt++) {
                asm volatile(
                    "mma.sync.aligned.m16n8k16.row.col.f32.f16.f16.f32 "
                    "{%0,%1,%2,%3}, {%4,%5,%6,%7}, {%8,%9}, {%0,%1,%2,%3};"
                    : "+f"(d[mt][nt][0]), "+f"(d[mt][nt][1]),
                      "+f"(d[mt][nt][2]), "+f"(d[mt][nt][3])
                    : "r"(a[mt][0]), "r"(a[mt][1]), "r"(a[mt][2]), "r"(a[mt][3]),
                      "r"(b[nt][0]), "r"(b[nt][1]));
            }
    }

    // Epilogue: fp32 to g_mat[n][i][j].
    float* M = g_mat + ((size_t)n << 20);
    int gi = lane >> 2;          // row group within m16
    int gj = (lane & 3) * 2;     // col pair within n8
#pragma unroll
    for (int mt = 0; mt < 2; mt++) {
#pragma unroll
        for (int nt = 0; nt < 4; nt++) {
            int i = i0 + wi + mt * 16 + gi;
            int j = j0 + wj + nt * 8 + gj;
            float2 v0 = make_float2(d[mt][nt][0], d[mt][nt][1]);
            float2 v1 = make_float2(d[mt][nt][2], d[mt][nt][3]);
            *(float2*)(M + (size_t)i * Ll + j)       = v0;
            *(float2*)(M + (size_t)(i + 8) * Ll + j) = v1;
        }
    }
}

// Gather: out[r][j] = 2 * M[n][t][idx].
__global__ void __launch_bounds__(128) gather_k(const int* __restrict__ neg_inds,
                                                float* __restrict__ out) {
    int r = blockIdx.x;
    int n = r >> 10;
    int t = r & (Ll - 1);
    int j = threadIdx.x;
    if (j > Kk) return;
    int idx = (j == 0) ? t : neg_inds[(size_t)r * Kk + j - 1];
    const float* M = g_mat + (((size_t)n << 20) + ((size_t)t << 10));
    out[(size_t)r * (Kk + 1) + j] = 2.0f * M[idx];
}

extern "C" void kernel_launch(void* const* d_in, const int* in_sizes, int n_in,
                              void* d_out, int out_size) {
    const float* z  = (const float*)d_in[0];  // [N, C, L]
    const float* c  = (const float*)d_in[1];  // [N, C, L+1]
    const int*   ni = (const int*)d_in[2];    // [N, L, K]
    float* out = (float*)d_out;               // [N*L, K+1]

    dim3 pg(Ll / 32, 2 * Nn);
    prep_k<<<pg, 256>>>(z, c);

    dim3 gg(Ll / 64, Ll / 64, Nn);
    gemm_k<<<gg, 128>>>();

    gather_k<<<Nn * Ll, 128>>>(ni, out);
}

// round 8
// speedup vs baseline: 1.1865x; 1.1865x over previous
#include <cuda_runtime.h>
#include <cuda_fp16.h>
#include <cstdint>

#define Nn 8
#define Cc 128
#define Ll 1024
#define Kk 100
#define EPSf 1e-8f

// Normalized fp16 rows, [N, L, C] (256B per row).
__device__ __half g_zh[Nn * Ll * Cc];
__device__ __half g_ch[Nn * Ll * Cc];

// Fused: transpose + norm + normalize + fp16 convert, one pass over the input.
// Sum-of-squares is accumulated during the load (each thread's elements share one t).
__global__ void __launch_bounds__(256) prep_k(const float* __restrict__ zsrc,
                                              const float* __restrict__ csrc) {
    __shared__ float tile[32][129];   // [t][ch]
    __shared__ float sp[8][32];
    __shared__ float srn[32];

    int zz = blockIdx.y;
    bool is_c = zz >= Nn;
    int n = is_c ? zz - Nn : zz;
    int ld      = is_c ? (Ll + 1) : Ll;
    int col_off = is_c ? 1 : 0;
    int t0 = blockIdx.x * 32;
    const float* s = (is_c ? csrc : zsrc) + (size_t)n * Cc * ld + col_off + t0;
    __half* d = (is_c ? g_ch : g_zh) + ((size_t)n * Ll + t0) * Cc;

    int tid = threadIdx.x;
    int tx  = tid & 31;    // t within tile
    int ty  = tid >> 5;    // 0..7

    // Load 16 channels for t=tx; accumulate sum-of-squares on the fly.
    float acc = 0.f;
#pragma unroll
    for (int i = 0; i < 16; i++) {
        int ch = i * 8 + ty;
        float v = s[(size_t)ch * ld + tx];
        tile[tx][ch] = v;
        acc += v * v;
    }
    sp[ty][tx] = acc;
    __syncthreads();

    if (tid < 32) {
        float sum = 0.f;
#pragma unroll
        for (int y = 0; y < 8; y++) sum += sp[y][tid];
        srn[tid] = 1.0f / fmaxf(sqrtf(sum), EPSf);
    }
    __syncthreads();

    // Write: 32 rows x 16 uint4; consecutive tid -> consecutive 16B (coalesced).
#pragma unroll
    for (int i = 0; i < 2; i++) {
        int linear = tid + i * 256;
        int t = linear >> 4;
        int k = linear & 15;
        float rn = srn[t];
        __half2 h[4];
#pragma unroll
        for (int q = 0; q < 4; q++) {
            float a = tile[t][k * 8 + 2 * q]     * rn;
            float b = tile[t][k * 8 + 2 * q + 1] * rn;
            h[q] = __floats2half2_rn(a, b);
        }
        ((uint4*)(d + (size_t)t * Cc))[k] = *(const uint4*)h;
    }
}

// Warp-per-row, 4 warps/block. 8 lanes per dot; lane p owns uint4 slots p and
// 8+p (contiguous 128B per 8-lane group). 4 dots/pass, 26 passes.
// Triple-buffered: prefetch 2 passes ahead (16 outstanding LDG.128 per warp).
__global__ void __launch_bounds__(128) main_k(const int* __restrict__ neg_inds,
                                              float* __restrict__ out) {
    int warp = threadIdx.x >> 5;
    int r    = (blockIdx.x << 2) + warp;   // 0..N*L-1
    int n    = r >> 10;
    int t    = r & (Ll - 1);
    int lane = threadIdx.x & 31;
    int g    = lane >> 3;                  // dot slot within pass
    int p    = lane & 7;                   // lane within dot

    // c chunk: 16 channels for this lane (slots p and 8+p), fp32 once.
    const uint4* crow = (const uint4*)(g_ch + (size_t)r * Cc);
    uint4 ca = crow[p], cb = crow[8 + p];
    float2 cf[8];
    {
        const __half2* h;
        h = (const __half2*)&ca;
        cf[0] = __half22float2(h[0]); cf[1] = __half22float2(h[1]);
        cf[2] = __half22float2(h[2]); cf[3] = __half22float2(h[3]);
        h = (const __half2*)&cb;
        cf[4] = __half22float2(h[0]); cf[5] = __half22float2(h[1]);
        cf[6] = __half22float2(h[2]); cf[7] = __half22float2(h[3]);
    }

    const uint4* zbase = (const uint4*)(g_zh + ((size_t)n << 10) * Cc);
    const int*   ni    = neg_inds + (size_t)r * Kk;
    float*       orow  = out + (size_t)r * (Kk + 1);

    // Prologue: passes 0 and 1.
    int idx0 = (g == 0) ? t : ni[g - 1];
    uint4 z0a = zbase[(size_t)idx0 * 16 + p];
    uint4 z0b = zbase[(size_t)idx0 * 16 + 8 + p];
    int idx1 = ni[3 + g];                    // j = 4+g (always a negative)
    uint4 z1a = zbase[(size_t)idx1 * 16 + p];
    uint4 z1b = zbase[(size_t)idx1 * 16 + 8 + p];

#pragma unroll
    for (int pass = 0; pass < 26; pass++) {
        int j = pass * 4 + g;

        // Prefetch pass+2 (slots j+8; never the positive unless dummy).
        uint4 ya, yb;
        if (pass < 24) {
            int jn   = j + 8;
            int idxn = (jn <= Kk) ? ni[jn - 1] : t;
            ya = zbase[(size_t)idxn * 16 + p];
            yb = zbase[(size_t)idxn * 16 + 8 + p];
        }

        float a = 0.f, b = 0.f;
        {
            const __half2* h = (const __half2*)&z0a;
#pragma unroll
            for (int q = 0; q < 4; q++) {
                float2 zf = __half22float2(h[q]);
                a = fmaf(cf[q].x, zf.x, a);
                b = fmaf(cf[q].y, zf.y, b);
            }
            h = (const __half2*)&z0b;
#pragma unroll
            for (int q = 0; q < 4; q++) {
                float2 zf = __half22float2(h[q]);
                a = fmaf(cf[4 + q].x, zf.x, a);
                b = fmaf(cf[4 + q].y, zf.y, b);
            }
        }
        a += b;

        a += __shfl_xor_sync(0xffffffffu, a, 1);
        a += __shfl_xor_sync(0xffffffffu, a, 2);
        a += __shfl_xor_sync(0xffffffffu, a, 4);

        if (p == 0 && j <= Kk)
            orow[j] = a * 2.0f;   // norms folded in; / TEMP = *2

        z0a = z1a; z0b = z1b;
        z1a = ya;  z1b = yb;
    }
}

extern "C" void kernel_launch(void* const* d_in, const int* in_sizes, int n_in,
                              void* d_out, int out_size) {
    const float* z  = (const float*)d_in[0];  // [N, C, L]
    const float* c  = (const float*)d_in[1];  // [N, C, L+1]
    const int*   ni = (const int*)d_in[2];    // [N, L, K]
    float* out = (float*)d_out;               // [N*L, K+1]

    dim3 pg(Ll / 32, 2 * Nn);
    prep_k<<<pg, 256>>>(z, c);

    main_k<<<(Nn * Ll) / 4, 128>>>(ni, out);
}

// round 9
// speedup vs baseline: 1.2921x; 1.0890x over previous
#include <cuda_runtime.h>
#include <cuda_fp16.h>
#include <cstdint>

#define Nn 8
#define Cc 128
#define Ll 1024
#define Kk 100
#define EPSf 1e-8f

// Normalized fp16 rows, [N, L, C] (256B per row).
__device__ __half g_zh[Nn * Ll * Cc];
__device__ __half g_ch[Nn * Ll * Cc];

// Fused: transpose + norm + normalize + fp16 convert, one pass over the input.
__global__ void __launch_bounds__(256) prep_k(const float* __restrict__ zsrc,
                                              const float* __restrict__ csrc) {
    __shared__ float tile[32][129];
    __shared__ float sp[8][32];
    __shared__ float srn[32];

    int zz = blockIdx.y;
    bool is_c = zz >= Nn;
    int n = is_c ? zz - Nn : zz;
    int ld      = is_c ? (Ll + 1) : Ll;
    int col_off = is_c ? 1 : 0;
    int t0 = blockIdx.x * 32;
    const float* s = (is_c ? csrc : zsrc) + (size_t)n * Cc * ld + col_off + t0;
    __half* d = (is_c ? g_ch : g_zh) + ((size_t)n * Ll + t0) * Cc;

    int tid = threadIdx.x;
    int tx  = tid & 31;
    int ty  = tid >> 5;

    float acc = 0.f;
#pragma unroll
    for (int i = 0; i < 16; i++) {
        int ch = i * 8 + ty;
        float v = s[(size_t)ch * ld + tx];
        tile[tx][ch] = v;
        acc += v * v;
    }
    sp[ty][tx] = acc;
    __syncthreads();

    if (tid < 32) {
        float sum = 0.f;
#pragma unroll
        for (int y = 0; y < 8; y++) sum += sp[y][tid];
        srn[tid] = 1.0f / fmaxf(sqrtf(sum), EPSf);
    }
    __syncthreads();

#pragma unroll
    for (int i = 0; i < 2; i++) {
        int linear = tid + i * 256;
        int t = linear >> 4;
        int k = linear & 15;
        float rn = srn[t];
        __half2 h[4];
#pragma unroll
        for (int q = 0; q < 4; q++) {
            float a = tile[t][k * 8 + 2 * q]     * rn;
            float b = tile[t][k * 8 + 2 * q + 1] * rn;
            h[q] = __floats2half2_rn(a, b);
        }
        ((uint4*)(d + (size_t)t * Cc))[k] = *(const uint4*)h;
    }
}

// Warp-per-row, 8 warps/block. 8 lanes per dot; lane p owns uint4 slots p and
// 8+p (one contiguous 128B line per 8-lane group per LDG).
// All 104 slot indices staged in smem up front (coalesced), so the inner loop
// has NO dependent global->global chain: LDS(idx, 1 it ahead) -> LDG(z, 2 it
// ahead) -> compute. 4 dots/pass, 26 passes.
__global__ void __launch_bounds__(256) main_k(const int* __restrict__ neg_inds,
                                              float* __restrict__ out) {
    __shared__ int sidx[8][108];

    int warp = threadIdx.x >> 5;
    int r    = (blockIdx.x << 3) + warp;   // 0..N*L-1
    int n    = r >> 10;
    int t    = r & (Ll - 1);
    int lane = threadIdx.x & 31;
    int g    = lane >> 3;                  // dot slot within pass
    int p    = lane & 7;                   // lane within dot

    // Stage indices: slot 0 = t (positive), 1..100 = negatives, 101..107 = t.
    const int* ni = neg_inds + (size_t)r * Kk;
    int* si = sidx[warp];
#pragma unroll
    for (int i = 0; i < 4; i++) {
        int jj = lane + 32 * i;            // 0..127
        if (jj < 108) si[jj] = (jj >= 1 && jj <= Kk) ? ni[jj - 1] : t;
    }
    __syncwarp();

    // c chunk: 16 channels for this lane (slots p and 8+p), fp32 once.
    const uint4* crow = (const uint4*)(g_ch + (size_t)r * Cc);
    uint4 ca = crow[p], cb = crow[8 + p];
    float2 cf[8];
    {
        const __half2* h;
        h = (const __half2*)&ca;
        cf[0] = __half22float2(h[0]); cf[1] = __half22float2(h[1]);
        cf[2] = __half22float2(h[2]); cf[3] = __half22float2(h[3]);
        h = (const __half2*)&cb;
        cf[4] = __half22float2(h[0]); cf[5] = __half22float2(h[1]);
        cf[6] = __half22float2(h[2]); cf[7] = __half22float2(h[3]);
    }

    const uint4* zbase = (const uint4*)(g_zh + ((size_t)n << 10) * Cc);
    float*       orow  = out + (size_t)r * (Kk + 1);

    // Prologue: z for passes 0,1; index register for pass 2's prefetch.
    int ia = si[g];
    uint4 z0a = zbase[(size_t)ia * 16 + p];
    uint4 z0b = zbase[(size_t)ia * 16 + 8 + p];
    int ib = si[4 + g];
    uint4 z1a = zbase[(size_t)ib * 16 + p];
    uint4 z1b = zbase[(size_t)ib * 16 + 8 + p];
    int ic = si[8 + g];

#pragma unroll
    for (int pass = 0; pass < 26; pass++) {
        int j = pass * 4 + g;

        // Prefetch z for pass+2 using the already-loaded index ic,
        // and fetch (LDS) the index for pass+3.
        uint4 ya, yb;
        if (pass < 24) {
            ya = zbase[(size_t)ic * 16 + p];
            yb = zbase[(size_t)ic * 16 + 8 + p];
        }
        if (pass < 23) ic = si[j + 12];

        float a = 0.f, b = 0.f;
        {
            const __half2* h = (const __half2*)&z0a;
#pragma unroll
            for (int q = 0; q < 4; q++) {
                float2 zf = __half22float2(h[q]);
                a = fmaf(cf[q].x, zf.x, a);
                b = fmaf(cf[q].y, zf.y, b);
            }
            h = (const __half2*)&z0b;
#pragma unroll
            for (int q = 0; q < 4; q++) {
                float2 zf = __half22float2(h[q]);
                a = fmaf(cf[4 + q].x, zf.x, a);
                b = fmaf(cf[4 + q].y, zf.y, b);
            }
        }
        a += b;

        a += __shfl_xor_sync(0xffffffffu, a, 1);
        a += __shfl_xor_sync(0xffffffffu, a, 2);
        a += __shfl_xor_sync(0xffffffffu, a, 4);

        if (p == 0 && j <= Kk)
            orow[j] = a * 2.0f;   // norms folded in; / TEMP = *2

        z0a = z1a; z0b = z1b;
        z1a = ya;  z1b = yb;
    }
}

extern "C" void kernel_launch(void* const* d_in, const int* in_sizes, int n_in,
                              void* d_out, int out_size) {
    const float* z  = (const float*)d_in[0];  // [N, C, L]
    const float* c  = (const float*)d_in[1];  // [N, C, L+1]
    const int*   ni = (const int*)d_in[2];    // [N, L, K]
    float* out = (float*)d_out;               // [N*L, K+1]

    dim3 pg(Ll / 32, 2 * Nn);
    prep_k<<<pg, 256>>>(z, c);

    main_k<<<(Nn * Ll) / 8, 256>>>(ni, out);
}